// round 7
// baseline (speedup 1.0000x reference)
#include <cuda_runtime.h>
#include <cstdint>
#include <cstddef>

// ---------------------------------------------------------------------------
// DataDependentRBFKernel — fully fused single kernel.
//   Block = 16 rows x full M (2048 pts), 256 threads, grid = 512.
//   Phase A: smem-staged sigma MLP for the block's 16 rows -> coef_s.
//   Phase B: RBF sweep, 4 pts/thread x 2 passes, packed f32x2 FMA.
// ---------------------------------------------------------------------------

#define EDIM 256
#define H1DIM 32
#define H2DIM 16
#define SROWS 16

typedef unsigned long long u64;

__device__ __forceinline__ float ex2_approx(float x) {
    float y;
    asm("ex2.approx.f32 %0, %1;" : "=f"(y) : "f"(x));
    return y;
}
__device__ __forceinline__ float gelu_exact(float x) {
    return 0.5f * x * (1.0f + erff(x * 0.70710678118654752440f));
}
__device__ __forceinline__ u64 pack2(float lo, float hi) {
    u64 r;
    asm("mov.b64 %0, {%1, %2};" : "=l"(r) : "f"(lo), "f"(hi));
    return r;
}
__device__ __forceinline__ void unpack2(u64 v, float& lo, float& hi) {
    asm("mov.b64 {%0, %1}, %2;" : "=f"(lo), "=f"(hi) : "l"(v));
}
__device__ __forceinline__ u64 fma2(u64 a, u64 b, u64 c) {
    u64 d;
    asm("fma.rn.f32x2 %0, %1, %2, %3;" : "=l"(d) : "l"(a), "l"(b), "l"(c));
    return d;
}
__device__ __forceinline__ u64 mul2(u64 a, u64 b) {
    u64 d;
    asm("mul.rn.f32x2 %0, %1, %2;" : "=l"(d) : "l"(a), "l"(b));
    return d;
}

// smem layout (floats):
//   e_s [16*256]=4096 | w1_s [256*32]=8192 ([k][j]) | w2_s [32*16]=512
//   h1_s [16*32]=512  | h2_s [16*16]=256 | coef_s float4[16]
#define SMEM_FLOATS (SROWS*EDIM + EDIM*H1DIM + H1DIM*H2DIM + SROWS*H1DIM + SROWS*H2DIM + SROWS*4)

__global__ __launch_bounds__(256)
void fused_kernel(const float* __restrict__ z, const float* __restrict__ mu,
                  const float* __restrict__ emb,
                  const float* __restrict__ w1, const float* __restrict__ b1,
                  const float* __restrict__ w2, const float* __restrict__ b2,
                  const float* __restrict__ w3, const float* __restrict__ b3,
                  float* __restrict__ out, int M)
{
    extern __shared__ float smem[];
    float*  e_s  = smem;                        // 4096
    float*  w1_s = e_s + SROWS * EDIM;          // 8192
    float*  w2_s = w1_s + EDIM * H1DIM;         // 512
    float*  h1_s = w2_s + H1DIM * H2DIM;        // 512
    float*  h2_s = h1_s + SROWS * H1DIM;        // 256
    float4* coef_s = reinterpret_cast<float4*>(h2_s + SROWS * H2DIM);

    const int tid = threadIdx.x;
    const int rowbase = blockIdx.x * SROWS;

    // ---- stage e (16 rows), w1, w2 ----
    {
        const float4* e4 = reinterpret_cast<const float4*>(emb + (size_t)rowbase * EDIM);
        float4* es4 = reinterpret_cast<float4*>(e_s);
        #pragma unroll
        for (int i = 0; i < (SROWS * EDIM / 4) / 256; ++i)   // 4
            es4[tid + i * 256] = e4[tid + i * 256];

        const float4* w14 = reinterpret_cast<const float4*>(w1);
        float4* w1s4 = reinterpret_cast<float4*>(w1_s);
        #pragma unroll
        for (int i = 0; i < (EDIM * H1DIM / 4) / 256; ++i)   // 8
            w1s4[tid + i * 256] = w14[tid + i * 256];

        if (tid < (H1DIM * H2DIM / 4))                        // 128
            reinterpret_cast<float4*>(w2_s)[tid] =
                reinterpret_cast<const float4*>(w2)[tid];
    }

    // ---- z for both passes into registers (packed pairs) ----
    u64 z0A0, z1A0, r2A0, z0B0, z1B0, r2B0;
    u64 z0A1, z1A1, r2A1, z0B1, z1B1, r2B1;
    {
        const float4* z4 = reinterpret_cast<const float4*>(z);
        float4 va, vb;
        va = __ldg(&z4[tid * 2]);       vb = __ldg(&z4[tid * 2 + 1]);
        z0A0 = pack2(va.x, va.z); z1A0 = pack2(va.y, va.w);
        z0B0 = pack2(vb.x, vb.z); z1B0 = pack2(vb.y, vb.w);
        va = __ldg(&z4[512 + tid * 2]); vb = __ldg(&z4[512 + tid * 2 + 1]);
        z0A1 = pack2(va.x, va.z); z1A1 = pack2(va.y, va.w);
        z0B1 = pack2(vb.x, vb.z); z1B1 = pack2(vb.y, vb.w);
        r2A0 = fma2(z1A0, z1A0, mul2(z0A0, z0A0));
        r2B0 = fma2(z1B0, z1B0, mul2(z0B0, z0B0));
        r2A1 = fma2(z1A1, z1A1, mul2(z0A1, z0A1));
        r2B1 = fma2(z1B1, z1B1, mul2(z0B1, z0B1));
    }
    __syncthreads();

    // ---- layer 1: warps 0-3, 4 rows each, lane = unit j ----
    if (tid < 128) {
        const int j = tid & 31;
        const int w = tid >> 5;            // 0..3
        const float* e0 = e_s + (w * 4) * EDIM;

        float acc0, acc1, acc2, acc3;
        acc0 = acc1 = acc2 = acc3 = __ldg(&b1[j]);

        #pragma unroll 8
        for (int k = 0; k < EDIM; k += 4) {
            const float wv0 = w1_s[(k + 0) * H1DIM + j];
            const float wv1 = w1_s[(k + 1) * H1DIM + j];
            const float wv2 = w1_s[(k + 2) * H1DIM + j];
            const float wv3 = w1_s[(k + 3) * H1DIM + j];
            float4 e;
            e = *reinterpret_cast<const float4*>(e0 + 0 * EDIM + k);
            acc0 = fmaf(e.x, wv0, acc0); acc0 = fmaf(e.y, wv1, acc0);
            acc0 = fmaf(e.z, wv2, acc0); acc0 = fmaf(e.w, wv3, acc0);
            e = *reinterpret_cast<const float4*>(e0 + 1 * EDIM + k);
            acc1 = fmaf(e.x, wv0, acc1); acc1 = fmaf(e.y, wv1, acc1);
            acc1 = fmaf(e.z, wv2, acc1); acc1 = fmaf(e.w, wv3, acc1);
            e = *reinterpret_cast<const float4*>(e0 + 2 * EDIM + k);
            acc2 = fmaf(e.x, wv0, acc2); acc2 = fmaf(e.y, wv1, acc2);
            acc2 = fmaf(e.z, wv2, acc2); acc2 = fmaf(e.w, wv3, acc2);
            e = *reinterpret_cast<const float4*>(e0 + 3 * EDIM + k);
            acc3 = fmaf(e.x, wv0, acc3); acc3 = fmaf(e.y, wv1, acc3);
            acc3 = fmaf(e.z, wv2, acc3); acc3 = fmaf(e.w, wv3, acc3);
        }
        h1_s[(w * 4 + 0) * H1DIM + j] = gelu_exact(acc0);
        h1_s[(w * 4 + 1) * H1DIM + j] = gelu_exact(acc1);
        h1_s[(w * 4 + 2) * H1DIM + j] = gelu_exact(acc2);
        h1_s[(w * 4 + 3) * H1DIM + j] = gelu_exact(acc3);
    }
    __syncthreads();

    // ---- layer 2: 16 rows x 16 units = 256 items, 1 per thread ----
    {
        const int r = tid >> 4;
        const int m = tid & 15;
        float acc = __ldg(&b2[m]);
        #pragma unroll
        for (int j = 0; j < H1DIM; ++j)
            acc = fmaf(h1_s[r * H1DIM + j], w2_s[j * H2DIM + m], acc);
        h2_s[r * H2DIM + m] = gelu_exact(acc);
    }
    __syncthreads();

    // ---- layer 3 + sigmoid + affine + fold mu -> coef_s ----
    if (tid < SROWS) {
        float s = __ldg(&b3[0]);
        #pragma unroll
        for (int m = 0; m < H2DIM; ++m)
            s = fmaf(h2_s[tid * H2DIM + m], __ldg(&w3[m]), s);
        const float sig = 1.0f / (1.0f + expf(-s));
        const float sigma = 0.1f + 9.9f * sig;
        const float sc = -1.44269504088896340736f / (2.0f * sigma * sigma);
        const float2 muv = reinterpret_cast<const float2*>(mu)[rowbase + tid];
        const float c0 = -2.0f * sc * muv.x;
        const float c1 = -2.0f * sc * muv.y;
        const float cc = sc * (muv.x * muv.x + muv.y * muv.y);
        coef_s[tid] = make_float4(sc, c0, c1, cc);
    }
    __syncthreads();

    // ---- sweep: 16 rows x 2 passes, 4 pts/thread/pass, FFMA2 ----
    float* ob = out + (size_t)rowbase * (size_t)M + (size_t)tid * 4;

    #pragma unroll
    for (int r = 0; r < SROWS; ++r) {
        const float4 c = coef_s[r];
        const u64 sc2 = pack2(c.x, c.x);
        const u64 c02 = pack2(c.y, c.y);
        const u64 c12 = pack2(c.z, c.z);
        const u64 cc2 = pack2(c.w, c.w);

        // pass 0 (pts tid*4 .. tid*4+3)
        {
            u64 aA = fma2(sc2, r2A0, fma2(c02, z0A0, fma2(c12, z1A0, cc2)));
            u64 aB = fma2(sc2, r2B0, fma2(c02, z0B0, fma2(c12, z1B0, cc2)));
            float a0, a1, a2, a3;
            unpack2(aA, a0, a1); unpack2(aB, a2, a3);
            *reinterpret_cast<float4*>(ob) =
                make_float4(ex2_approx(a0), ex2_approx(a1),
                            ex2_approx(a2), ex2_approx(a3));
        }
        // pass 1 (pts 1024 + tid*4 ..)
        {
            u64 aA = fma2(sc2, r2A1, fma2(c02, z0A1, fma2(c12, z1A1, cc2)));
            u64 aB = fma2(sc2, r2B1, fma2(c02, z0B1, fma2(c12, z1B1, cc2)));
            float a0, a1, a2, a3;
            unpack2(aA, a0, a1); unpack2(aB, a2, a3);
            *reinterpret_cast<float4*>(ob + 1024) =
                make_float4(ex2_approx(a0), ex2_approx(a1),
                            ex2_approx(a2), ex2_approx(a3));
        }
        ob += M;
    }
}

// ---------------------------------------------------------------------------
extern "C" void kernel_launch(void* const* d_in, const int* in_sizes, int n_in,
                              void* d_out, int out_size)
{
    const float* z   = (const float*)d_in[0];   // [M, 2]
    const float* mu  = (const float*)d_in[1];   // [B, N, 2]
    const float* emb = (const float*)d_in[2];   // [B, N, 256]
    const float* w1  = (const float*)d_in[3];   // [256, 32]
    const float* b1  = (const float*)d_in[4];   // [32]
    const float* w2  = (const float*)d_in[5];   // [32, 16]
    const float* b2  = (const float*)d_in[6];   // [16]
    const float* w3  = (const float*)d_in[7];   // [16, 1]
    const float* b3  = (const float*)d_in[8];   // [1]
    float* out = (float*)d_out;

    const int M  = in_sizes[0] / 2;   // 2048
    const int BN = in_sizes[1] / 2;   // 8192

    const int smem_bytes = SMEM_FLOATS * sizeof(float);
    static bool attr_set = false;
    if (!attr_set) {
        cudaFuncSetAttribute(fused_kernel,
                             cudaFuncAttributeMaxDynamicSharedMemorySize,
                             smem_bytes);
        attr_set = true;
    }

    fused_kernel<<<BN / SROWS, 256, smem_bytes>>>(z, mu, emb, w1, b1, w2, b2,
                                                  w3, b3, out, M);
}

// round 10
// speedup vs baseline: 1.1250x; 1.1250x over previous
#include <cuda_runtime.h>
#include <cstdint>
#include <cstddef>

// ---------------------------------------------------------------------------
// DataDependentRBFKernel — producer/consumer fused single kernel.
//   Blocks 0..255     : producers. 32 sigma rows each (MLP 256->32->16->1),
//                       write (sc,c0,c1,cc) to g_coef, release flag.
//   Blocks 256..2303  : consumers. Proven sweep shape: 8 rows x 1024 z,
//                       4 pts/thread. Spin on producer flag (generation-
//                       counter scheme -> graph-replay safe, no resets).
// ---------------------------------------------------------------------------

#define EDIM 256
#define H1DIM 32
#define H2DIM 16
#define PROWS 32          // rows per producer block

__device__ float4       g_coef[8192];
__device__ unsigned int g_flag[256];      // producer completion counters
__device__ unsigned int g_consgen[2048];  // per-consumer-block generation

__device__ __forceinline__ float ex2_approx(float x) {
    float y;
    asm("ex2.approx.f32 %0, %1;" : "=f"(y) : "f"(x));
    return y;
}
__device__ __forceinline__ float gelu_exact(float x) {
    return 0.5f * x * (1.0f + erff(x * 0.70710678118654752440f));
}
// L2-scoped vector load (no L1) for coefficients written by another CTA.
__device__ __forceinline__ float4 ld_cg_f4(const float4* p) {
    float4 v;
    asm volatile("ld.global.cg.v4.f32 {%0, %1, %2, %3}, [%4];"
                 : "=f"(v.x), "=f"(v.y), "=f"(v.z), "=f"(v.w) : "l"(p));
    return v;
}

__global__ __launch_bounds__(256)
void fused_kernel(const float* __restrict__ z, const float* __restrict__ mu,
                  const float* __restrict__ emb,
                  const float* __restrict__ w1, const float* __restrict__ b1,
                  const float* __restrict__ w2, const float* __restrict__ b2,
                  const float* __restrict__ w3, const float* __restrict__ b3,
                  float* __restrict__ out, int M)
{
    __shared__ float w1_s[EDIM * H1DIM];    // 32 KB  [k][j], j contiguous
    __shared__ float w2_s[H1DIM * H2DIM];   // 2 KB
    __shared__ float h1_s[PROWS * H1DIM];   // 4 KB
    __shared__ float h2_s[PROWS * H2DIM];   // 2 KB

    const int tid = threadIdx.x;

    if (blockIdx.x < 256) {
        // ================= PRODUCER =================
        const int rowbase = blockIdx.x * PROWS;

        // stage w1 (2048 float4 / 256 thr), w2
        {
            const float4* w14 = reinterpret_cast<const float4*>(w1);
            float4* w1s4 = reinterpret_cast<float4*>(w1_s);
            #pragma unroll
            for (int i = 0; i < (EDIM * H1DIM / 4) / 256; ++i)   // 8
                w1s4[tid + i * 256] = w14[tid + i * 256];
            if (tid < (H1DIM * H2DIM / 4))
                reinterpret_cast<float4*>(w2_s)[tid] =
                    reinterpret_cast<const float4*>(w2)[tid];
        }
        __syncthreads();

        // layer 1: warp w -> rows 4w..4w+3, lane = unit j; e via LDG broadcast
        {
            const int j = tid & 31;
            const int w = tid >> 5;            // 0..7
            const float* e0 = emb + (size_t)(rowbase + w * 4) * EDIM;

            float acc0, acc1, acc2, acc3;
            acc0 = acc1 = acc2 = acc3 = __ldg(&b1[j]);

            #pragma unroll 8
            for (int k = 0; k < EDIM; k += 4) {
                const float wv0 = w1_s[(k + 0) * H1DIM + j];
                const float wv1 = w1_s[(k + 1) * H1DIM + j];
                const float wv2 = w1_s[(k + 2) * H1DIM + j];
                const float wv3 = w1_s[(k + 3) * H1DIM + j];
                float4 e;
                e = __ldg(reinterpret_cast<const float4*>(e0 + 0 * EDIM + k));
                acc0 = fmaf(e.x, wv0, acc0); acc0 = fmaf(e.y, wv1, acc0);
                acc0 = fmaf(e.z, wv2, acc0); acc0 = fmaf(e.w, wv3, acc0);
                e = __ldg(reinterpret_cast<const float4*>(e0 + 1 * EDIM + k));
                acc1 = fmaf(e.x, wv0, acc1); acc1 = fmaf(e.y, wv1, acc1);
                acc1 = fmaf(e.z, wv2, acc1); acc1 = fmaf(e.w, wv3, acc1);
                e = __ldg(reinterpret_cast<const float4*>(e0 + 2 * EDIM + k));
                acc2 = fmaf(e.x, wv0, acc2); acc2 = fmaf(e.y, wv1, acc2);
                acc2 = fmaf(e.z, wv2, acc2); acc2 = fmaf(e.w, wv3, acc2);
                e = __ldg(reinterpret_cast<const float4*>(e0 + 3 * EDIM + k));
                acc3 = fmaf(e.x, wv0, acc3); acc3 = fmaf(e.y, wv1, acc3);
                acc3 = fmaf(e.z, wv2, acc3); acc3 = fmaf(e.w, wv3, acc3);
            }
            h1_s[(w * 4 + 0) * H1DIM + j] = gelu_exact(acc0);
            h1_s[(w * 4 + 1) * H1DIM + j] = gelu_exact(acc1);
            h1_s[(w * 4 + 2) * H1DIM + j] = gelu_exact(acc2);
            h1_s[(w * 4 + 3) * H1DIM + j] = gelu_exact(acc3);
        }
        __syncthreads();

        // layer 2: 32 rows x 16 units = 512 items, 2 per thread
        {
            #pragma unroll
            for (int it = 0; it < 2; ++it) {
                const int item = tid + it * 256;
                const int r = item >> 4;
                const int m = item & 15;
                float acc = __ldg(&b2[m]);
                #pragma unroll
                for (int jj = 0; jj < H1DIM; ++jj)
                    acc = fmaf(h1_s[r * H1DIM + jj], w2_s[jj * H2DIM + m], acc);
                h2_s[r * H2DIM + m] = gelu_exact(acc);
            }
        }
        __syncthreads();

        // layer 3 + sigmoid + affine + fold mu; write coefs
        if (tid < PROWS) {
            float s = __ldg(&b3[0]);
            #pragma unroll
            for (int m = 0; m < H2DIM; ++m)
                s = fmaf(h2_s[tid * H2DIM + m], __ldg(&w3[m]), s);
            const float sig = 1.0f / (1.0f + expf(-s));
            const float sigma = 0.1f + 9.9f * sig;
            const float sc = -1.44269504088896340736f / (2.0f * sigma * sigma);
            const float2 muv = reinterpret_cast<const float2*>(mu)[rowbase + tid];
            const float c0 = -2.0f * sc * muv.x;
            const float c1 = -2.0f * sc * muv.y;
            const float cc = sc * (muv.x * muv.x + muv.y * muv.y);
            g_coef[rowbase + tid] = make_float4(sc, c0, c1, cc);
        }
        __syncthreads();

        // release: fence then bump flag (monotone across graph replays)
        if (tid == 0) {
            __threadfence();
            atomicAdd(&g_flag[blockIdx.x], 1u);
        }
    } else {
        // ================= CONSUMER =================
        const int cb = blockIdx.x - 256;
        const int xb = cb & 1;             // z half: 0 or 1
        const int rg = cb >> 1;            // row group (8 rows)
        const int rowbase = rg * 8;
        const int p = rowbase >> 5;        // producer index

        // z loads first (overlap latency with the spin)
        float z0[4], z1[4], r2[4];
        {
            const float4* z4 = reinterpret_cast<const float4*>(z);
            #pragma unroll
            for (int i = 0; i < 2; ++i) {
                float4 v = __ldg(&z4[(size_t)(xb * 512) + (size_t)tid * 2 + i]);
                z0[2 * i]     = v.x;  z1[2 * i]     = v.y;
                z0[2 * i + 1] = v.z;  z1[2 * i + 1] = v.w;
            }
            #pragma unroll
            for (int i = 0; i < 4; ++i)
                r2[i] = z0[i] * z0[i] + z1[i] * z1[i];
        }

        // wait for producer (generation-counter scheme; replay-safe)
        if (tid == 0) {
            const unsigned exp = atomicAdd(&g_consgen[cb], 1u) + 1u;
            while (*reinterpret_cast<volatile unsigned*>(&g_flag[p]) < exp)
                __nanosleep(64);
        }
        __syncthreads();
        __threadfence();   // order flag observation before coef reads

        const int zb = xb * 1024 + tid * 4;
        float* optr = out + (size_t)rowbase * (size_t)M + (size_t)zb;

        #pragma unroll
        for (int r = 0; r < 8; ++r) {
            const float4 c = ld_cg_f4(&g_coef[rowbase + r]);
            float o[4];
            #pragma unroll
            for (int i = 0; i < 4; ++i) {
                float a = fmaf(c.x, r2[i], fmaf(c.y, z0[i], fmaf(c.z, z1[i], c.w)));
                o[i] = ex2_approx(a);
            }
            *reinterpret_cast<float4*>(optr) = make_float4(o[0], o[1], o[2], o[3]);
            optr += M;
        }
    }
}

// ---------------------------------------------------------------------------
extern "C" void kernel_launch(void* const* d_in, const int* in_sizes, int n_in,
                              void* d_out, int out_size)
{
    const float* z   = (const float*)d_in[0];   // [M, 2]
    const float* mu  = (const float*)d_in[1];   // [B, N, 2]
    const float* emb = (const float*)d_in[2];   // [B, N, 256]
    const float* w1  = (const float*)d_in[3];   // [256, 32]
    const float* b1  = (const float*)d_in[4];   // [32]
    const float* w2  = (const float*)d_in[5];   // [32, 16]
    const float* b2  = (const float*)d_in[6];   // [16]
    const float* w3  = (const float*)d_in[7];   // [16, 1]
    const float* b3  = (const float*)d_in[8];   // [1]
    float* out = (float*)d_out;

    const int M  = in_sizes[0] / 2;   // 2048
    const int BN = in_sizes[1] / 2;   // 8192

    const int n_prod = BN / PROWS;              // 256
    const int n_cons = (BN / 8) * (M / 1024);   // 2048

    fused_kernel<<<n_prod + n_cons, 256>>>(z, mu, emb, w1, b1, w2, b2,
                                           w3, b3, out, M);
}